// round 15
// baseline (speedup 1.0000x reference)
#include <cuda_runtime.h>
#include <cstdint>

// ---------------------------------------------------------------------------
// MultiheadAttention (B=4, S=4096, D=1024).
//   Wk_eff = Wh@Wk ; bk_eff = bh@Wk + bk   (folded double projection)
//   Wv_eff = Wh@Wv ; bv_eff = bh@Wv + bv
//   q = Q@Wh+bh ; k = K@Wk_eff+bk_eff ; v = V@Wv_eff+bv_eff
//   S = q k^T / 1024 ; P = softmax(S) ; O = P v ; out = O@Wo+bo
// GEMMs: mma.sync m16n8k8 tf32, 3xTF32 compensation. hi/lo split done ONCE
// at smem staging (float2 tiles), inner loop is pure LDS.64 + MMA.
// 128x128x8 double-buffered tiles, 8 warps, warp tile 32x64.
// LDH=12: (12*r+qq) mod 16 is a perfect half-warp partition -> conflict-free.
// ---------------------------------------------------------------------------

#define BM 128
#define BN 128
#define BK 8
#define LDH 12

__device__ float g_q[16777216];
__device__ float g_k[16777216];
__device__ float g_v[16777216];
__device__ float g_t[16777216];
__device__ float g_s[67108864];
__device__ float g_wk[1048576];
__device__ float g_wv[1048576];
__device__ float g_bk[1024];
__device__ float g_bv[1024];

__device__ __forceinline__ float2 split2(float x)
{
    uint32_t hi;
    asm("cvt.rna.tf32.f32 %0, %1;" : "=r"(hi) : "f"(x));
    float h = __uint_as_float(hi);
    float l = x - h;
    uint32_t lo;
    asm("cvt.rna.tf32.f32 %0, %1;" : "=r"(lo) : "f"(l));
    return make_float2(h, __uint_as_float(lo));
}

#define MMA_TF32(d, a, b)                                                     \
    asm volatile(                                                             \
        "mma.sync.aligned.m16n8k8.row.col.f32.tf32.tf32.f32 "                 \
        "{%0,%1,%2,%3}, {%4,%5,%6,%7}, {%8,%9}, {%0,%1,%2,%3};"               \
        : "+f"((d)[0]), "+f"((d)[1]), "+f"((d)[2]), "+f"((d)[3])              \
        : "r"((a)[0]), "r"((a)[1]), "r"((a)[2]), "r"((a)[3]),                 \
          "r"((b)[0]), "r"((b)[1]))

// ---------------- NN: C[M,N] = A[M,K] @ B[K,N] (+bias), batched -------------
__global__ __launch_bounds__(256, 2)
void gemm_nn_tc(const float* __restrict__ A, const float* __restrict__ B,
                const float* __restrict__ bias, float* __restrict__ C,
                int M, int N, int K,
                long long aB, long long bB, long long cB)
{
    __shared__ float2 As2[2][BM * LDH];
    __shared__ float2 Bs2[2][BN * LDH];
    A += aB * (long long)blockIdx.z;
    B += bB * (long long)blockIdx.z;
    C += cB * (long long)blockIdx.z;

    const int t = threadIdx.x, lane = t & 31, wid = t >> 5;
    const int warpM = wid & 3, warpN = wid >> 2;   // 4 x 2 warps
    const int r = lane >> 2, qq = lane & 3;

    const int sm = t >> 1, ska = (t & 1) << 2;     // A: row, k-offset
    const int sn = t & 127, skb = (t >> 7) << 2;   // B: col, k-offset
    const float* Ap = A + (long long)(blockIdx.y * BM + sm) * K + ska;
    const float* Bp = B + blockIdx.x * BN + sn;

    // preload tile 0 (split at staging)
    {
        float4 a = *(const float4*)Ap;
        float2 s0 = split2(a.x), s1 = split2(a.y), s2 = split2(a.z), s3 = split2(a.w);
        float2* da = &As2[0][sm * LDH + ska];
        *(float4*)(da)     = make_float4(s0.x, s0.y, s1.x, s1.y);
        *(float4*)(da + 2) = make_float4(s2.x, s2.y, s3.x, s3.y);
        float2 u0 = split2(Bp[(long long)(skb + 0) * N]);
        float2 u1 = split2(Bp[(long long)(skb + 1) * N]);
        float2 u2 = split2(Bp[(long long)(skb + 2) * N]);
        float2 u3 = split2(Bp[(long long)(skb + 3) * N]);
        float2* db = &Bs2[0][sn * LDH + skb];
        *(float4*)(db)     = make_float4(u0.x, u0.y, u1.x, u1.y);
        *(float4*)(db + 2) = make_float4(u2.x, u2.y, u3.x, u3.y);
    }
    __syncthreads();

    float acc[2][8][4] = {};
    int p = 0;

    for (int k0 = 0; k0 < K; k0 += BK) {
        const bool next = (k0 + BK) < K;
        float4 pa;
        float pb[4];
        if (next) {
            pa = *(const float4*)(Ap + k0 + BK);
#pragma unroll
            for (int j = 0; j < 4; j++)
                pb[j] = Bp[(long long)(k0 + BK + skb + j) * N];
        }

        uint32_t bhi[8][2], blo[8][2];
#pragma unroll
        for (int bn = 0; bn < 8; bn++) {
            const int nb = warpN * 64 + bn * 8 + r;
            uint2 x = *(const uint2*)&Bs2[p][nb * LDH + qq];
            uint2 y = *(const uint2*)&Bs2[p][nb * LDH + qq + 4];
            bhi[bn][0] = x.x; blo[bn][0] = x.y;
            bhi[bn][1] = y.x; blo[bn][1] = y.y;
        }
#pragma unroll
        for (int am = 0; am < 2; am++) {
            const int mb = warpM * 32 + am * 16;
            uint2 a0 = *(const uint2*)&As2[p][(mb + r    ) * LDH + qq];
            uint2 a1 = *(const uint2*)&As2[p][(mb + r + 8) * LDH + qq];
            uint2 a2 = *(const uint2*)&As2[p][(mb + r    ) * LDH + qq + 4];
            uint2 a3 = *(const uint2*)&As2[p][(mb + r + 8) * LDH + qq + 4];
            uint32_t ahi[4] = {a0.x, a1.x, a2.x, a3.x};
            uint32_t alo[4] = {a0.y, a1.y, a2.y, a3.y};
#pragma unroll
            for (int bn = 0; bn < 8; bn++) {
                MMA_TF32(acc[am][bn], ahi, blo[bn]);
                MMA_TF32(acc[am][bn], alo, bhi[bn]);
                MMA_TF32(acc[am][bn], ahi, bhi[bn]);
            }
        }

        if (next) {
            float2 s0 = split2(pa.x), s1 = split2(pa.y), s2 = split2(pa.z), s3 = split2(pa.w);
            float2* da = &As2[1 - p][sm * LDH + ska];
            *(float4*)(da)     = make_float4(s0.x, s0.y, s1.x, s1.y);
            *(float4*)(da + 2) = make_float4(s2.x, s2.y, s3.x, s3.y);
            float2 u0 = split2(pb[0]), u1 = split2(pb[1]);
            float2 u2 = split2(pb[2]), u3 = split2(pb[3]);
            float2* db = &Bs2[1 - p][sn * LDH + skb];
            *(float4*)(db)     = make_float4(u0.x, u0.y, u1.x, u1.y);
            *(float4*)(db + 2) = make_float4(u2.x, u2.y, u3.x, u3.y);
        }
        __syncthreads();
        p ^= 1;
    }

    const int row0 = blockIdx.y * BM + warpM * 32;
    const int col0 = blockIdx.x * BN + warpN * 64;
#pragma unroll
    for (int am = 0; am < 2; am++) {
        const int r0 = row0 + am * 16 + r;
#pragma unroll
        for (int bn = 0; bn < 8; bn++) {
            const int col = col0 + bn * 8 + (qq << 1);
            float b0 = 0.f, b1 = 0.f;
            if (bias) { b0 = bias[col]; b1 = bias[col + 1]; }
            float2 o0 = make_float2(acc[am][bn][0] + b0, acc[am][bn][1] + b1);
            float2 o1 = make_float2(acc[am][bn][2] + b0, acc[am][bn][3] + b1);
            *(float2*)&C[(long long)r0 * N + col]       = o0;
            *(float2*)&C[(long long)(r0 + 8) * N + col] = o1;
        }
    }
}

// ---------------- NT: C[M,N] = scale * A[M,K] @ B[N,K]^T, batched -----------
__global__ __launch_bounds__(256, 2)
void gemm_nt_tc(const float* __restrict__ A, const float* __restrict__ B,
                float* __restrict__ C, int M, int N, int K, float scale,
                long long aB, long long bB, long long cB)
{
    __shared__ float2 As2[2][BM * LDH];
    __shared__ float2 Bs2[2][BN * LDH];
    A += aB * (long long)blockIdx.z;
    B += bB * (long long)blockIdx.z;
    C += cB * (long long)blockIdx.z;

    const int t = threadIdx.x, lane = t & 31, wid = t >> 5;
    const int warpM = wid & 3, warpN = wid >> 2;
    const int r = lane >> 2, qq = lane & 3;

    const int sm = t >> 1, ska = (t & 1) << 2;
    const float* Ap = A + (long long)(blockIdx.y * BM + sm) * K + ska;
    const float* Bp = B + (long long)(blockIdx.x * BN + sm) * K + ska;  // [N,K] rows

    {
        float4 a = *(const float4*)Ap;
        float2 s0 = split2(a.x), s1 = split2(a.y), s2 = split2(a.z), s3 = split2(a.w);
        float2* da = &As2[0][sm * LDH + ska];
        *(float4*)(da)     = make_float4(s0.x, s0.y, s1.x, s1.y);
        *(float4*)(da + 2) = make_float4(s2.x, s2.y, s3.x, s3.y);
        float4 b = *(const float4*)Bp;
        float2 u0 = split2(b.x), u1 = split2(b.y), u2 = split2(b.z), u3 = split2(b.w);
        float2* db = &Bs2[0][sm * LDH + ska];
        *(float4*)(db)     = make_float4(u0.x, u0.y, u1.x, u1.y);
        *(float4*)(db + 2) = make_float4(u2.x, u2.y, u3.x, u3.y);
    }
    __syncthreads();

    float acc[2][8][4] = {};
    int p = 0;

    for (int k0 = 0; k0 < K; k0 += BK) {
        const bool next = (k0 + BK) < K;
        float4 pa, pb;
        if (next) {
            pa = *(const float4*)(Ap + k0 + BK);
            pb = *(const float4*)(Bp + k0 + BK);
        }

        uint32_t bhi[8][2], blo[8][2];
#pragma unroll
        for (int bn = 0; bn < 8; bn++) {
            const int nb = warpN * 64 + bn * 8 + r;
            uint2 x = *(const uint2*)&Bs2[p][nb * LDH + qq];
            uint2 y = *(const uint2*)&Bs2[p][nb * LDH + qq + 4];
            bhi[bn][0] = x.x; blo[bn][0] = x.y;
            bhi[bn][1] = y.x; blo[bn][1] = y.y;
        }
#pragma unroll
        for (int am = 0; am < 2; am++) {
            const int mb = warpM * 32 + am * 16;
            uint2 a0 = *(const uint2*)&As2[p][(mb + r    ) * LDH + qq];
            uint2 a1 = *(const uint2*)&As2[p][(mb + r + 8) * LDH + qq];
            uint2 a2 = *(const uint2*)&As2[p][(mb + r    ) * LDH + qq + 4];
            uint2 a3 = *(const uint2*)&As2[p][(mb + r + 8) * LDH + qq + 4];
            uint32_t ahi[4] = {a0.x, a1.x, a2.x, a3.x};
            uint32_t alo[4] = {a0.y, a1.y, a2.y, a3.y};
#pragma unroll
            for (int bn = 0; bn < 8; bn++) {
                MMA_TF32(acc[am][bn], ahi, blo[bn]);
                MMA_TF32(acc[am][bn], alo, bhi[bn]);
                MMA_TF32(acc[am][bn], ahi, bhi[bn]);
            }
        }

        if (next) {
            float2 s0 = split2(pa.x), s1 = split2(pa.y), s2 = split2(pa.z), s3 = split2(pa.w);
            float2* da = &As2[1 - p][sm * LDH + ska];
            *(float4*)(da)     = make_float4(s0.x, s0.y, s1.x, s1.y);
            *(float4*)(da + 2) = make_float4(s2.x, s2.y, s3.x, s3.y);
            float2 u0 = split2(pb.x), u1 = split2(pb.y), u2 = split2(pb.z), u3 = split2(pb.w);
            float2* db = &Bs2[1 - p][sm * LDH + ska];
            *(float4*)(db)     = make_float4(u0.x, u0.y, u1.x, u1.y);
            *(float4*)(db + 2) = make_float4(u2.x, u2.y, u3.x, u3.y);
        }
        __syncthreads();
        p ^= 1;
    }

    const int row0 = blockIdx.y * BM + warpM * 32;
    const int col0 = blockIdx.x * BN + warpN * 64;
#pragma unroll
    for (int am = 0; am < 2; am++) {
        const int r0 = row0 + am * 16 + r;
#pragma unroll
        for (int bn = 0; bn < 8; bn++) {
            const int col = col0 + bn * 8 + (qq << 1);
            float2 o0 = make_float2(acc[am][bn][0] * scale, acc[am][bn][1] * scale);
            float2 o1 = make_float2(acc[am][bn][2] * scale, acc[am][bn][3] * scale);
            *(float2*)&C[(long long)r0 * N + col]       = o0;
            *(float2*)&C[(long long)(r0 + 8) * N + col] = o1;
        }
    }
}

// ----- bias fold: outb[n] = sum_d bh[d]*W[d][n] + b[n]  (D=1024) ------------
__global__ __launch_bounds__(256)
void bias_fold(const float* __restrict__ bh, const float* __restrict__ W,
               const float* __restrict__ b, float* __restrict__ outb)
{
    const int n = blockIdx.x * 256 + threadIdx.x;
    float s = b[n];
#pragma unroll 8
    for (int d = 0; d < 1024; d++)
        s += bh[d] * W[d * 1024 + n];
    outb[n] = s;
}

// ------------- softmax over rows of length 4096, one block/row --------------
__global__ __launch_bounds__(256)
void softmax_rows(float* __restrict__ S)
{
    __shared__ float red[256];
    float* p = S + (long long)blockIdx.x * 4096;
    const int t = threadIdx.x;

    float4 v[4];
    float m = -1e30f;
#pragma unroll
    for (int i = 0; i < 4; i++) {
        v[i] = ((const float4*)p)[t + (i << 8)];
        m = fmaxf(m, fmaxf(fmaxf(v[i].x, v[i].y), fmaxf(v[i].z, v[i].w)));
    }
    red[t] = m;
    __syncthreads();
    for (int s = 128; s > 0; s >>= 1) {
        if (t < s) red[t] = fmaxf(red[t], red[t + s]);
        __syncthreads();
    }
    m = red[0];
    __syncthreads();

    float sum = 0.f;
#pragma unroll
    for (int i = 0; i < 4; i++) {
        v[i].x = __expf(v[i].x - m);
        v[i].y = __expf(v[i].y - m);
        v[i].z = __expf(v[i].z - m);
        v[i].w = __expf(v[i].w - m);
        sum += v[i].x + v[i].y + v[i].z + v[i].w;
    }
    red[t] = sum;
    __syncthreads();
    for (int s = 128; s > 0; s >>= 1) {
        if (t < s) red[t] += red[t + s];
        __syncthreads();
    }
    float inv = 1.0f / red[0];

#pragma unroll
    for (int i = 0; i < 4; i++) {
        v[i].x *= inv;
        v[i].y *= inv;
        v[i].z *= inv;
        v[i].w *= inv;
        ((float4*)p)[t + (i << 8)] = v[i];
    }
}

extern "C" void kernel_launch(void* const* d_in, const int* in_sizes, int n_in,
                              void* d_out, int out_size)
{
    (void)in_sizes; (void)n_in; (void)out_size;
    const float* query = (const float*)d_in[0];
    const float* key   = (const float*)d_in[1];
    const float* value = (const float*)d_in[2];
    const float* Wh    = (const float*)d_in[3];
    const float* bh    = (const float*)d_in[4];
    const float* Wk    = (const float*)d_in[5];
    const float* bk    = (const float*)d_in[6];
    const float* Wv    = (const float*)d_in[7];
    const float* bv    = (const float*)d_in[8];
    const float* Wo    = (const float*)d_in[9];
    const float* bo    = (const float*)d_in[10];
    float* out = (float*)d_out;

    float *q, *k, *v, *tm, *s, *wk, *wv, *bke, *bve;
    cudaGetSymbolAddress((void**)&q,   g_q);
    cudaGetSymbolAddress((void**)&k,   g_k);
    cudaGetSymbolAddress((void**)&v,   g_v);
    cudaGetSymbolAddress((void**)&tm,  g_t);
    cudaGetSymbolAddress((void**)&s,   g_s);
    cudaGetSymbolAddress((void**)&wk,  g_wk);
    cudaGetSymbolAddress((void**)&wv,  g_wv);
    cudaGetSymbolAddress((void**)&bke, g_bk);
    cudaGetSymbolAddress((void**)&bve, g_bv);

    const long long SD = 4096LL * 1024;
    const long long SS = 4096LL * 4096;

    // fold double projections: Wk_eff = Wh@Wk, bk_eff = bh@Wk + bk (same for V)
    dim3 gw(1024 / BN, 1024 / BM);
    gemm_nn_tc<<<gw, 256>>>(Wh, Wk, nullptr, wk, 1024, 1024, 1024, 0, 0, 0);
    gemm_nn_tc<<<gw, 256>>>(Wh, Wv, nullptr, wv, 1024, 1024, 1024, 0, 0, 0);
    bias_fold<<<4, 256>>>(bh, Wk, bk, bke);
    bias_fold<<<4, 256>>>(bh, Wv, bv, bve);

    dim3 gp(1024 / BN, 16384 / BM);       // projections (M = B*S = 16384)
    gemm_nn_tc<<<gp, 256>>>(query, Wh, bh,  q, 16384, 1024, 1024, 0, 0, 0);
    gemm_nn_tc<<<gp, 256>>>(key,   wk, bke, k, 16384, 1024, 1024, 0, 0, 0);
    gemm_nn_tc<<<gp, 256>>>(value, wv, bve, v, 16384, 1024, 1024, 0, 0, 0);

    dim3 gs(4096 / BN, 4096 / BM, 4);     // scores = q k^T / 1024
    gemm_nt_tc<<<gs, 256>>>(q, k, s, 4096, 4096, 1024, 1.0f / 1024.0f, SD, SD, SS);

    softmax_rows<<<4 * 4096, 256>>>(s);

    dim3 go(1024 / BN, 4096 / BM, 4);     // O = P @ v
    gemm_nn_tc<<<go, 256>>>(s, v, nullptr, tm, 4096, 1024, 4096, SS, SD, SD);

    gemm_nn_tc<<<gp, 256>>>(tm, Wo, bo, out, 16384, 1024, 1024, 0, 0, 0);
}

// round 17
// speedup vs baseline: 1.2306x; 1.2306x over previous
#include <cuda_runtime.h>
#include <cstdint>

// ---------------------------------------------------------------------------
// MultiheadAttention (B=4, S=4096, D=1024).
//   Wk_eff = Wh@Wk ; bk_eff = bh@Wk + bk   (folded double projection)
//   Wv_eff = Wh@Wv ; bv_eff = bh@Wv + bv
//   q = Q@Wh+bh ; k = K@Wk_eff+bk_eff ; v = V@Wv_eff+bv_eff
//   S = q k^T / 1024 ; P = softmax(S) ; O = P v ; out = O@Wo+bo
// GEMM core: the ROUND-8 MEASURED kernel (7923us total, 572us/GEMM):
// mma.sync m16n8k8 tf32 3xTF32, per-fragment split, 128x128x16 double-buffered,
// 8 warps, warp tile 32x64, no min-blocks clamp (126 regs, no spills).
// ---------------------------------------------------------------------------

#define BM 128
#define BN 128
#define BK 16
#define LDA 20    // As[m][k] stride: conflict-free frag loads, float4-aligned
#define LDB_NN 17 // Bs[n][k] stride (NN: scalar k-major staging)
#define LDB_NT 20 // Bs[n][k] stride (NT: float4 staging)

__device__ float g_q[16777216];
__device__ float g_k[16777216];
__device__ float g_v[16777216];
__device__ float g_t[16777216];
__device__ float g_s[67108864];
__device__ float g_wk[1048576];
__device__ float g_wv[1048576];
__device__ float g_bk[1024];
__device__ float g_bv[1024];

__device__ __forceinline__ void split_tf32(float x, uint32_t& hi, uint32_t& lo)
{
    asm("cvt.rna.tf32.f32 %0, %1;" : "=r"(hi) : "f"(x));
    float l = x - __uint_as_float(hi);
    asm("cvt.rna.tf32.f32 %0, %1;" : "=r"(lo) : "f"(l));
}

#define MMA_TF32(d, a, b)                                                     \
    asm volatile(                                                             \
        "mma.sync.aligned.m16n8k8.row.col.f32.tf32.tf32.f32 "                 \
        "{%0,%1,%2,%3}, {%4,%5,%6,%7}, {%8,%9}, {%0,%1,%2,%3};"               \
        : "+f"((d)[0]), "+f"((d)[1]), "+f"((d)[2]), "+f"((d)[3])              \
        : "r"((a)[0]), "r"((a)[1]), "r"((a)[2]), "r"((a)[3]),                 \
          "r"((b)[0]), "r"((b)[1]))

// ---------------- NN: C[M,N] = A[M,K] @ B[K,N] (+bias), batched -------------
__global__ __launch_bounds__(256)
void gemm_nn_tc(const float* __restrict__ A, const float* __restrict__ B,
                const float* __restrict__ bias, float* __restrict__ C,
                int M, int N, int K,
                long long aB, long long bB, long long cB)
{
    __shared__ float As[2][BM * LDA];
    __shared__ float Bs[2][BN * LDB_NN];
    A += aB * (long long)blockIdx.z;
    B += bB * (long long)blockIdx.z;
    C += cB * (long long)blockIdx.z;

    const int t = threadIdx.x, lane = t & 31, wid = t >> 5;
    const int warpM = wid & 3, warpN = wid >> 2;   // 4 x 2 warps
    const int r = lane >> 2, qq = lane & 3;

    const int am0 = t >> 2,        ak0 = (t & 3) << 2;
    const int am1 = (t + 256) >> 2, ak1 = ((t + 256) & 3) << 2;
    const float* ApBase = A + (long long)(blockIdx.y * BM) * K;
    const int bn0 = t & 127,         bkb0 = (t >> 7) << 2;
    const int bn1 = (t + 256) & 127, bkb1 = ((t + 256) >> 7) << 2;
    const float* BpBase = B + blockIdx.x * BN;

    {
        float4 a0 = *(const float4*)(ApBase + (long long)am0 * K + ak0);
        float4 a1 = *(const float4*)(ApBase + (long long)am1 * K + ak1);
        *(float4*)&As[0][am0 * LDA + ak0] = a0;
        *(float4*)&As[0][am1 * LDA + ak1] = a1;
#pragma unroll
        for (int j = 0; j < 4; j++) {
            Bs[0][bn0 * LDB_NN + bkb0 + j] = BpBase[(long long)(bkb0 + j) * N + bn0];
            Bs[0][bn1 * LDB_NN + bkb1 + j] = BpBase[(long long)(bkb1 + j) * N + bn1];
        }
    }
    __syncthreads();

    float acc[2][8][4] = {};
    int p = 0;

    for (int k0 = 0; k0 < K; k0 += BK) {
        const bool next = (k0 + BK) < K;
        float4 pa0, pa1;
        float  pb0[4], pb1[4];
        if (next) {
            pa0 = *(const float4*)(ApBase + (long long)am0 * K + k0 + BK + ak0);
            pa1 = *(const float4*)(ApBase + (long long)am1 * K + k0 + BK + ak1);
#pragma unroll
            for (int j = 0; j < 4; j++) {
                pb0[j] = BpBase[(long long)(k0 + BK + bkb0 + j) * N + bn0];
                pb1[j] = BpBase[(long long)(k0 + BK + bkb1 + j) * N + bn1];
            }
        }

#pragma unroll
        for (int c = 0; c < 2; c++) {
            const int k8 = c * 8;
            uint32_t ahi[2][4], alo[2][4];
#pragma unroll
            for (int am = 0; am < 2; am++) {
                const int mb = warpM * 32 + am * 16;
                float f0 = As[p][(mb + r    ) * LDA + k8 + qq    ];
                float f1 = As[p][(mb + r + 8) * LDA + k8 + qq    ];
                float f2 = As[p][(mb + r    ) * LDA + k8 + qq + 4];
                float f3 = As[p][(mb + r + 8) * LDA + k8 + qq + 4];
                split_tf32(f0, ahi[am][0], alo[am][0]);
                split_tf32(f1, ahi[am][1], alo[am][1]);
                split_tf32(f2, ahi[am][2], alo[am][2]);
                split_tf32(f3, ahi[am][3], alo[am][3]);
            }
            uint32_t bhi[8][2], blo[8][2];
#pragma unroll
            for (int bn = 0; bn < 8; bn++) {
                const int nb = warpN * 64 + bn * 8 + r;
                float g0 = Bs[p][nb * LDB_NN + k8 + qq    ];
                float g1 = Bs[p][nb * LDB_NN + k8 + qq + 4];
                split_tf32(g0, bhi[bn][0], blo[bn][0]);
                split_tf32(g1, bhi[bn][1], blo[bn][1]);
            }
#pragma unroll
            for (int am = 0; am < 2; am++)
#pragma unroll
                for (int bn = 0; bn < 8; bn++) {
                    MMA_TF32(acc[am][bn], ahi[am], blo[bn]);
                    MMA_TF32(acc[am][bn], alo[am], bhi[bn]);
                    MMA_TF32(acc[am][bn], ahi[am], bhi[bn]);
                }
        }

        if (next) {
            *(float4*)&As[1 - p][am0 * LDA + ak0] = pa0;
            *(float4*)&As[1 - p][am1 * LDA + ak1] = pa1;
#pragma unroll
            for (int j = 0; j < 4; j++) {
                Bs[1 - p][bn0 * LDB_NN + bkb0 + j] = pb0[j];
                Bs[1 - p][bn1 * LDB_NN + bkb1 + j] = pb1[j];
            }
        }
        __syncthreads();
        p ^= 1;
    }

    const int row0 = blockIdx.y * BM + warpM * 32;
    const int col0 = blockIdx.x * BN + warpN * 64;
#pragma unroll
    for (int am = 0; am < 2; am++) {
        const int r0 = row0 + am * 16 + r;
#pragma unroll
        for (int bn = 0; bn < 8; bn++) {
            const int col = col0 + bn * 8 + (qq << 1);
            float b0 = 0.f, b1 = 0.f;
            if (bias) { b0 = bias[col]; b1 = bias[col + 1]; }
            float2 o0 = make_float2(acc[am][bn][0] + b0, acc[am][bn][1] + b1);
            float2 o1 = make_float2(acc[am][bn][2] + b0, acc[am][bn][3] + b1);
            *(float2*)&C[(long long)r0 * N + col]       = o0;
            *(float2*)&C[(long long)(r0 + 8) * N + col] = o1;
        }
    }
}

// ---------------- NT: C[M,N] = scale * A[M,K] @ B[N,K]^T, batched -----------
__global__ __launch_bounds__(256)
void gemm_nt_tc(const float* __restrict__ A, const float* __restrict__ B,
                float* __restrict__ C, int M, int N, int K, float scale,
                long long aB, long long bB, long long cB)
{
    __shared__ float As[2][BM * LDA];
    __shared__ float Bs[2][BN * LDB_NT];
    A += aB * (long long)blockIdx.z;
    B += bB * (long long)blockIdx.z;
    C += cB * (long long)blockIdx.z;

    const int t = threadIdx.x, lane = t & 31, wid = t >> 5;
    const int warpM = wid & 3, warpN = wid >> 2;
    const int r = lane >> 2, qq = lane & 3;

    const int am0 = t >> 2,         ak0 = (t & 3) << 2;
    const int am1 = (t + 256) >> 2, ak1 = ((t + 256) & 3) << 2;
    const float* ApBase = A + (long long)(blockIdx.y * BM) * K;
    const float* BpBase = B + (long long)(blockIdx.x * BN) * K;  // [N,K] rows

    {
        float4 a0 = *(const float4*)(ApBase + (long long)am0 * K + ak0);
        float4 a1 = *(const float4*)(ApBase + (long long)am1 * K + ak1);
        *(float4*)&As[0][am0 * LDA + ak0] = a0;
        *(float4*)&As[0][am1 * LDA + ak1] = a1;
        float4 b0 = *(const float4*)(BpBase + (long long)am0 * K + ak0);
        float4 b1 = *(const float4*)(BpBase + (long long)am1 * K + ak1);
        *(float4*)&Bs[0][am0 * LDB_NT + ak0] = b0;
        *(float4*)&Bs[0][am1 * LDB_NT + ak1] = b1;
    }
    __syncthreads();

    float acc[2][8][4] = {};
    int p = 0;

    for (int k0 = 0; k0 < K; k0 += BK) {
        const bool next = (k0 + BK) < K;
        float4 pa0, pa1, pb0, pb1;
        if (next) {
            pa0 = *(const float4*)(ApBase + (long long)am0 * K + k0 + BK + ak0);
            pa1 = *(const float4*)(ApBase + (long long)am1 * K + k0 + BK + ak1);
            pb0 = *(const float4*)(BpBase + (long long)am0 * K + k0 + BK + ak0);
            pb1 = *(const float4*)(BpBase + (long long)am1 * K + k0 + BK + ak1);
        }

#pragma unroll
        for (int c = 0; c < 2; c++) {
            const int k8 = c * 8;
            uint32_t ahi[2][4], alo[2][4];
#pragma unroll
            for (int am = 0; am < 2; am++) {
                const int mb = warpM * 32 + am * 16;
                float f0 = As[p][(mb + r    ) * LDA + k8 + qq    ];
                float f1 = As[p][(mb + r + 8) * LDA + k8 + qq    ];
                float f2 = As[p][(mb + r    ) * LDA + k8 + qq + 4];
                float f3 = As[p][(mb + r + 8) * LDA + k8 + qq + 4];
                split_tf32(f0, ahi[am][0], alo[am][0]);
                split_tf32(f1, ahi[am][1], alo[am][1]);
                split_tf32(f2, ahi[am][2], alo[am][2]);
                split_tf32(f3, ahi[am][3], alo[am][3]);
            }
            uint32_t bhi[8][2], blo[8][2];
#pragma unroll
            for (int bn = 0; bn < 8; bn++) {
                const int nb = warpN * 64 + bn * 8 + r;
                float g0 = Bs[p][nb * LDB_NT + k8 + qq    ];
                float g1 = Bs[p][nb * LDB_NT + k8 + qq + 4];
                split_tf32(g0, bhi[bn][0], blo[bn][0]);
                split_tf32(g1, bhi[bn][1], blo[bn][1]);
            }
#pragma unroll
            for (int am = 0; am < 2; am++)
#pragma unroll
                for (int bn = 0; bn < 8; bn++) {
                    MMA_TF32(acc[am][bn], ahi[am], blo[bn]);
                    MMA_TF32(acc[am][bn], alo[am], bhi[bn]);
                    MMA_TF32(acc[am][bn], ahi[am], bhi[bn]);
                }
        }

        if (next) {
            *(float4*)&As[1 - p][am0 * LDA + ak0] = pa0;
            *(float4*)&As[1 - p][am1 * LDA + ak1] = pa1;
            *(float4*)&Bs[1 - p][am0 * LDB_NT + ak0] = pb0;
            *(float4*)&Bs[1 - p][am1 * LDB_NT + ak1] = pb1;
        }
        __syncthreads();
        p ^= 1;
    }

    const int row0 = blockIdx.y * BM + warpM * 32;
    const int col0 = blockIdx.x * BN + warpN * 64;
#pragma unroll
    for (int am = 0; am < 2; am++) {
        const int r0 = row0 + am * 16 + r;
#pragma unroll
        for (int bn = 0; bn < 8; bn++) {
            const int col = col0 + bn * 8 + (qq << 1);
            float2 o0 = make_float2(acc[am][bn][0] * scale, acc[am][bn][1] * scale);
            float2 o1 = make_float2(acc[am][bn][2] * scale, acc[am][bn][3] * scale);
            *(float2*)&C[(long long)r0 * N + col]       = o0;
            *(float2*)&C[(long long)(r0 + 8) * N + col] = o1;
        }
    }
}

// ----- bias fold: outb[n] = sum_d bh[d]*W[d][n] + b[n]; one block per n -----
__global__ __launch_bounds__(256)
void bias_fold(const float* __restrict__ bh, const float* __restrict__ W,
               const float* __restrict__ b, float* __restrict__ outb)
{
    __shared__ float red[256];
    const int n = blockIdx.x;
    const int t = threadIdx.x;
    float s = 0.f;
#pragma unroll
    for (int d = t; d < 1024; d += 256)
        s += bh[d] * W[(long long)d * 1024 + n];
    red[t] = s;
    __syncthreads();
    for (int q = 128; q > 0; q >>= 1) {
        if (t < q) red[t] += red[t + q];
        __syncthreads();
    }
    if (t == 0) outb[n] = red[0] + b[n];
}

// ------------- softmax over rows of length 4096, one block/row --------------
__global__ __launch_bounds__(256)
void softmax_rows(float* __restrict__ S)
{
    __shared__ float red[256];
    float* p = S + (long long)blockIdx.x * 4096;
    const int t = threadIdx.x;

    float4 v[4];
    float m = -1e30f;
#pragma unroll
    for (int i = 0; i < 4; i++) {
        v[i] = ((const float4*)p)[t + (i << 8)];
        m = fmaxf(m, fmaxf(fmaxf(v[i].x, v[i].y), fmaxf(v[i].z, v[i].w)));
    }
    red[t] = m;
    __syncthreads();
    for (int s = 128; s > 0; s >>= 1) {
        if (t < s) red[t] = fmaxf(red[t], red[t + s]);
        __syncthreads();
    }
    m = red[0];
    __syncthreads();

    float sum = 0.f;
#pragma unroll
    for (int i = 0; i < 4; i++) {
        v[i].x = __expf(v[i].x - m);
        v[i].y = __expf(v[i].y - m);
        v[i].z = __expf(v[i].z - m);
        v[i].w = __expf(v[i].w - m);
        sum += v[i].x + v[i].y + v[i].z + v[i].w;
    }
    red[t] = sum;
    __syncthreads();
    for (int s = 128; s > 0; s >>= 1) {
        if (t < s) red[t] += red[t + s];
        __syncthreads();
    }
    float inv = 1.0f / red[0];

#pragma unroll
    for (int i = 0; i < 4; i++) {
        v[i].x *= inv;
        v[i].y *= inv;
        v[i].z *= inv;
        v[i].w *= inv;
        ((float4*)p)[t + (i << 8)] = v[i];
    }
}

extern "C" void kernel_launch(void* const* d_in, const int* in_sizes, int n_in,
                              void* d_out, int out_size)
{
    (void)in_sizes; (void)n_in; (void)out_size;
    const float* query = (const float*)d_in[0];
    const float* key   = (const float*)d_in[1];
    const float* value = (const float*)d_in[2];
    const float* Wh    = (const float*)d_in[3];
    const float* bh    = (const float*)d_in[4];
    const float* Wk    = (const float*)d_in[5];
    const float* bk    = (const float*)d_in[6];
    const float* Wv    = (const float*)d_in[7];
    const float* bv    = (const float*)d_in[8];
    const float* Wo    = (const float*)d_in[9];
    const float* bo    = (const float*)d_in[10];
    float* out = (float*)d_out;

    float *q, *k, *v, *tm, *s, *wk, *wv, *bke, *bve;
    cudaGetSymbolAddress((void**)&q,   g_q);
    cudaGetSymbolAddress((void**)&k,   g_k);
    cudaGetSymbolAddress((void**)&v,   g_v);
    cudaGetSymbolAddress((void**)&tm,  g_t);
    cudaGetSymbolAddress((void**)&s,   g_s);
    cudaGetSymbolAddress((void**)&wk,  g_wk);
    cudaGetSymbolAddress((void**)&wv,  g_wv);
    cudaGetSymbolAddress((void**)&bke, g_bk);
    cudaGetSymbolAddress((void**)&bve, g_bv);

    const long long SD = 4096LL * 1024;
    const long long SS = 4096LL * 4096;

    // fold double projections: Wk_eff = Wh@Wk, bk_eff = bh@Wk + bk (same for V)
    dim3 gw(1024 / BN, 1024 / BM);
    gemm_nn_tc<<<gw, 256>>>(Wh, Wk, nullptr, wk, 1024, 1024, 1024, 0, 0, 0);   // launch 1
    gemm_nn_tc<<<gw, 256>>>(Wh, Wv, nullptr, wv, 1024, 1024, 1024, 0, 0, 0);   // launch 2
    bias_fold<<<1024, 256>>>(bh, Wk, bk, bke);                                  // launch 3
    bias_fold<<<1024, 256>>>(bh, Wv, bv, bve);                                  // launch 4

    dim3 gp(1024 / BN, 16384 / BM);       // projections (M = B*S = 16384)
    gemm_nn_tc<<<gp, 256>>>(query, Wh, bh,  q, 16384, 1024, 1024, 0, 0, 0);    // launch 5
    gemm_nn_tc<<<gp, 256>>>(key,   wk, bke, k, 16384, 1024, 1024, 0, 0, 0);    // launch 6 (ncu capture)
    gemm_nn_tc<<<gp, 256>>>(value, wv, bve, v, 16384, 1024, 1024, 0, 0, 0);

    dim3 gs(4096 / BN, 4096 / BM, 4);     // scores = q k^T / 1024
    gemm_nt_tc<<<gs, 256>>>(q, k, s, 4096, 4096, 1024, 1.0f / 1024.0f, SD, SD, SS);

    softmax_rows<<<4 * 4096, 256>>>(s);

    dim3 go(1024 / BN, 4096 / BM, 4);     // O = P @ v
    gemm_nn_tc<<<go, 256>>>(s, v, nullptr, tm, 4096, 1024, 4096, SS, SD, SD);

    gemm_nn_tc<<<gp, 256>>>(tm, Wo, bo, out, 16384, 1024, 1024, 0, 0, 0);
}